// round 17
// baseline (speedup 1.0000x reference)
#include <cuda_runtime.h>
#include <cuda_fp16.h>
#include <cstdint>

// ============================================================================
// TernaryConv2d as shift-GEMM, row-pair tiles, software-pipelined slab loads:
//   out[co] = alpha[co]*sum_{kh,kw}( x_shift[pix,ci] @ B(kh,kw)[co,ci]^T ) + bias
// Per CTA-tile = TWO output rows: M=448 pixels, N=64, nine K=64 GEMMs.
// Padded input rows live as fp16 [wp][ci] SW128 slabs in a ring of 4.
// Next pair's 2 slabs are LDG'd + packed to h2 during this pair's MMA blocks
// and stored into ring slots as they are vacated (kh-major order + 2 mid
// barriers). Prefetch held PACKED (28 u32/thread) to avoid register spill.
// ============================================================================

#define HW        224
#define NHW       50176
#define NCHW1     3211264
#define PAIRS_TOTAL 1792         // 16*224/2
#define K_TOTAL   576

#define SLAB_STRIDE 29696        // >= 226*128
#define SLAB_BYTES  28928        // 226 rows * 128B
#define OFF_B       0            // 9 * 8192 = 73728
#define OFF_CONST   73728        // alpha[64], bias[64]
#define OFF_SLAB    74752
#define SMEM_BYTES  (OFF_SLAB + 4 * SLAB_STRIDE)   // 193536

#define SW128(o) ((o) ^ (((o) >> 3) & 0x70))

// Scratch (allocation-free rule: __device__ globals)
__device__ __align__(16) unsigned char g_Bsw[9 * 8192];
__device__ float g_alpha[64];

// ============================================================================
// helpers
// ============================================================================
__device__ __forceinline__ uint32_t smem_to_u32(const void* p) {
    uint32_t a;
    asm("{ .reg .u64 t; cvta.to.shared.u64 t, %1; cvt.u32.u64 %0, t; }"
        : "=r"(a) : "l"(p));
    return a;
}
__device__ __forceinline__ void ldsm_x4(uint32_t* r, uint32_t addr) {
    asm volatile("ldmatrix.sync.aligned.m8n8.x4.shared.b16 {%0,%1,%2,%3}, [%4];"
        : "=r"(r[0]), "=r"(r[1]), "=r"(r[2]), "=r"(r[3]) : "r"(addr));
}
__device__ __forceinline__ void ldsm_x4_t(uint32_t* r, uint32_t addr) {
    asm volatile("ldmatrix.sync.aligned.m8n8.x4.trans.shared.b16 {%0,%1,%2,%3}, [%4];"
        : "=r"(r[0]), "=r"(r[1]), "=r"(r[2]), "=r"(r[3]) : "r"(addr));
}
__device__ __forceinline__ void mma16816(float* c, const uint32_t* a, const uint32_t* b) {
    asm volatile(
        "mma.sync.aligned.m16n8k16.row.col.f32.f16.f16.f32 "
        "{%0,%1,%2,%3}, {%4,%5,%6,%7}, {%8,%9}, {%0,%1,%2,%3};"
        : "+f"(c[0]), "+f"(c[1]), "+f"(c[2]), "+f"(c[3])
        : "r"(a[0]), "r"(a[1]), "r"(a[2]), "r"(a[3]), "r"(b[0]), "r"(b[1]));
}
__device__ __forceinline__ uint32_t pack_h2(float lo, float hi) {
    __half2 h = __floats2half2_rn(lo, hi);
    return *reinterpret_cast<uint32_t*>(&h);
}

// ============================================================================
// Prep: TWN ternarize. g_alpha[co]; g_Bsw per gemm g=kh*3+kw:
// [ci=64 rows][128B of co halves] SW128 tile at offset g*8192.
// ============================================================================
__global__ void prep_ternarize(const float* __restrict__ w) {
    const int co = blockIdx.x;
    const float* wc = w + co * K_TOTAL;
    const int tid = threadIdx.x, lane = tid & 31, warp = tid >> 5;

    __shared__ float r1[8], r2[8], r3[8];
    __shared__ float sh_delta;

    float s = 0.f;
    for (int k = tid; k < K_TOTAL; k += 256) s += fabsf(wc[k]);
    #pragma unroll
    for (int o = 16; o; o >>= 1) s += __shfl_xor_sync(0xffffffffu, s, o);
    if (lane == 0) r1[warp] = s;
    __syncthreads();
    if (tid == 0) {
        float tot = 0.f;
        #pragma unroll
        for (int i = 0; i < 8; i++) tot += r1[i];
        sh_delta = (0.7f / 576.f) * tot;
    }
    __syncthreads();
    const float delta = sh_delta;

    float ms = 0.f, mc = 0.f;
    for (int k = tid; k < K_TOTAL; k += 256) {
        float a = fabsf(wc[k]);
        if (a > delta) { ms += a; mc += 1.f; }
    }
    #pragma unroll
    for (int o = 16; o; o >>= 1) {
        ms += __shfl_xor_sync(0xffffffffu, ms, o);
        mc += __shfl_xor_sync(0xffffffffu, mc, o);
    }
    if (lane == 0) { r2[warp] = ms; r3[warp] = mc; }
    __syncthreads();
    if (tid == 0) {
        float tms = 0.f, tmc = 0.f;
        #pragma unroll
        for (int i = 0; i < 8; i++) { tms += r2[i]; tmc += r3[i]; }
        if (tmc < 0.5f) tmc = 1.f;
        float al = tms / tmc;
        if (al < 1e-4f) al = 1e-4f;
        g_alpha[co] = al;
    }

    for (int k = tid; k < K_TOTAL; k += 256) {
        float wv = wc[k];
        float tv = (wv > delta) ? 1.f : ((wv < -delta) ? -1.f : 0.f);
        unsigned ci = (unsigned)k / 9u;
        unsigned g  = (unsigned)k - ci * 9u;    // kh*3+kw
        unsigned off = g * 8192u + SW128(ci * 128u + (unsigned)co * 2u);
        *reinterpret_cast<__half*>(g_Bsw + off) = __float2half_rn(tv);
    }
}

// ============================================================================
// Slab helpers. Slab layout: [wp=0..225] rows of 128B (64 ci halves), SW128.
// Warp owns ci [wid*8, +8); lanes stride w (coalesced). v4 stores: the 4 ci
// pairs are 16 contiguous bytes under SW128 (cib*2 is 16B aligned).
// ============================================================================
__device__ __forceinline__ void slab_pads(uint32_t slot, int cib, int lane) {
    if (lane < 4) {   // zero wp=0 / wp=225 pad pixels for this warp's ci
        const uint32_t c2 = (uint32_t)(cib + lane * 2) * 2u;
        asm volatile("st.shared.b32 [%0], %1;"
            :: "r"(slot + SW128(c2)), "r"(0u) : "memory");
        asm volatile("st.shared.b32 [%0], %1;"
            :: "r"(slot + SW128((225u << 7) + c2)), "r"(0u) : "memory");
    }
}

// Immediate (blocking) slab load: padded row p (input u=p-1) -> ring slot p&3.
__device__ __forceinline__ void load_slab(uint32_t sb, const float* __restrict__ x,
                                          int n, int p, int tid) {
    const uint32_t slot = sb + OFF_SLAB + (uint32_t)(p & 3) * SLAB_STRIDE;
    const int u = p - 1;
    const int lane = tid & 31;
    const int cib = (tid >> 5) * 8;
    if ((unsigned)u < (unsigned)HW) {
        const float* bp = x + (size_t)(n * 64 + cib) * NHW + (size_t)u * HW;
        #pragma unroll
        for (int wb = 0; wb < 7; wb++) {
            const int w = wb * 32 + lane;
            uint32_t h2v[4];
            #pragma unroll
            for (int cp = 0; cp < 4; cp++) {
                const float* p0 = bp + (size_t)(cp * 2) * NHW;
                h2v[cp] = pack_h2(__ldg(p0 + w), __ldg(p0 + NHW + w));
            }
            const uint32_t off = SW128(((uint32_t)(w + 1) << 7) + (uint32_t)cib * 2u);
            asm volatile("st.shared.v4.b32 [%0], {%1,%2,%3,%4};"
                :: "r"(slot + off), "r"(h2v[0]), "r"(h2v[1]), "r"(h2v[2]), "r"(h2v[3])
                : "memory");
        }
        slab_pads(slot, cib, lane);
    } else {
        for (int i = tid; i < SLAB_BYTES / 16; i += 256) {
            asm volatile("st.shared.v4.b32 [%0], {%1,%2,%3,%4};"
                :: "r"(slot + (uint32_t)i * 16), "r"(0u), "r"(0u), "r"(0u), "r"(0u)
                : "memory");
        }
    }
}

// Prefetch: LDG input row u and PACK to 28 h2 regs (8 fp32 transiently live).
__device__ __forceinline__ void pf_issue(uint32_t* ph, const float* __restrict__ x,
                                         int n, int u, int cib, int lane, bool ok) {
    const float* bp = x + (size_t)(n * 64 + cib) * NHW
                        + (size_t)(ok ? u : 0) * HW;
    #pragma unroll
    for (int wb = 0; wb < 7; wb++) {
        const int w = wb * 32 + lane;
        #pragma unroll
        for (int cp = 0; cp < 4; cp++) {
            const float* p0 = bp + (size_t)(cp * 2) * NHW;
            float lo = ok ? __ldg(p0 + w) : 0.f;
            float hi = ok ? __ldg(p0 + NHW + w) : 0.f;
            ph[wb * 4 + cp] = pack_h2(lo, hi);
        }
    }
}

// Store 28 packed h2 into ring slot (plus pad pixels).
__device__ __forceinline__ void pf_store(uint32_t slot, const uint32_t* ph,
                                         int cib, int lane) {
    #pragma unroll
    for (int wb = 0; wb < 7; wb++) {
        const int w = wb * 32 + lane;
        const uint32_t off = SW128(((uint32_t)(w + 1) << 7) + (uint32_t)cib * 2u);
        asm volatile("st.shared.v4.b32 [%0], {%1,%2,%3,%4};"
            :: "r"(slot + off), "r"(ph[wb * 4]), "r"(ph[wb * 4 + 1]),
               "r"(ph[wb * 4 + 2]), "r"(ph[wb * 4 + 3])
            : "memory");
    }
    slab_pads(slot, cib, lane);
}

// ============================================================================
// Main kernel: persistent CTAs walk contiguous row-pair ranges.
// 8 warps: wm=wid>>1 -> (output row r_sel=wm>>1, half (wm&1)*112); wn=wid&1.
// ============================================================================
__global__ void __launch_bounds__(256, 1)
ternary_conv_kernel(const float* __restrict__ x,
                    const float* __restrict__ bias,
                    float* __restrict__ out) {
    extern __shared__ __align__(1024) unsigned char smem[];
    const uint32_t sb = smem_to_u32(smem);
    const int tid  = threadIdx.x;
    const int lane = tid & 31;
    const int wid  = tid >> 5;
    const int lm = lane & 15, lh = lane >> 4;
    const int wn = wid & 1;
    const int wm = wid >> 1;
    const int r_sel  = wm >> 1;
    const int mbase  = (wm & 1) * 112;
    const int nbase  = wn * 32;
    const int cib    = wid * 8;            // slab-load ci base

    // one-time: B image + alpha/bias into SMEM
    {
        const uint4* src = reinterpret_cast<const uint4*>(g_Bsw);
        uint4* dst = reinterpret_cast<uint4*>(smem + OFF_B);
        #pragma unroll
        for (int i = 0; i < 18; i++) dst[tid + i * 256] = src[tid + i * 256];
    }
    if (tid < 64) {
        *reinterpret_cast<float*>(smem + OFF_CONST + tid * 4) = g_alpha[tid];
        *reinterpret_cast<float*>(smem + OFF_CONST + 256 + tid * 4) = bias[tid];
    }

    // A/B address constants (SW128 XOR hoisted)
    uint32_t rbase[7];
    #pragma unroll
    for (int i = 0; i < 7; i++)
        rbase[i] = ((uint32_t)(mbase + i * 16 + lm) << 7) + (uint32_t)lh * 16;
    uint32_t vkw[3];
    #pragma unroll
    for (int kw = 0; kw < 3; kw++)
        vkw[kw] = ((uint32_t)((lm + kw) & 7)) << 4;
    const uint32_t blane = ((uint32_t)lm << 7) + (uint32_t)(nbase + lh * 8) * 2u;
    const uint32_t vb = ((uint32_t)(lm & 7)) << 4;
    const uint32_t bB = sb + OFF_B + blane;

    __syncthreads();

    const int nb = gridDim.x;
    const int q0 = (int)(((long long)PAIRS_TOTAL * blockIdx.x) / nb);
    const int q1 = (int)(((long long)PAIRS_TOTAL * (blockIdx.x + 1)) / nb);

    bool have = false;
    #pragma unroll 1
    for (int q = q0; q < q1; ++q) {
        const int n  = q / 112;
        const int h0 = (q - n * 112) * 2;

        if (!have) {
            __syncthreads();
            load_slab(sb, x, n, h0 + 0, tid);
            load_slab(sb, x, n, h0 + 1, tid);
            load_slab(sb, x, n, h0 + 2, tid);
            load_slab(sb, x, n, h0 + 3, tid);
            __syncthreads();
        }
        const bool same = (q + 1 < q1) && (((q + 1) % 112) != 0);

        uint32_t sA[3];
        #pragma unroll
        for (int kh = 0; kh < 3; kh++)
            sA[kh] = sb + OFF_SLAB
                   + (uint32_t)((h0 + r_sel + kh) & 3) * SLAB_STRIDE;

        float acc[112];
        #pragma unroll
        for (int i = 0; i < 112; i++) acc[i] = 0.f;

        #define GEMM_BLOCK(KH, KW) do {                                         \
            const uint32_t bg = bB + (uint32_t)((KH) * 3 + (KW)) * 8192u;       \
            const uint32_t ap = sA[KH] + ((uint32_t)(KW) << 7);                 \
            _Pragma("unroll")                                                   \
            for (int s = 0; s < 4; s++) {                                       \
                uint32_t bf[8];                                                 \
                ldsm_x4_t(bf,     (bg + (uint32_t)s * 2048u) ^ vb);             \
                ldsm_x4_t(bf + 4, (bg + (uint32_t)s * 2048u + 32u) ^ vb);       \
                const uint32_t pre = ap + (uint32_t)s * 32u;                    \
                _Pragma("unroll")                                               \
                for (int i = 0; i < 7; i++) {                                   \
                    uint32_t af[4];                                             \
                    ldsm_x4(af, (rbase[i] + pre) ^ vkw[KW]);                    \
                    mma16816(acc + i * 16,      af, bf);                        \
                    mma16816(acc + i * 16 + 4,  af, bf + 2);                    \
                    mma16816(acc + i * 16 + 8,  af, bf + 4);                    \
                    mma16816(acc + i * 16 + 12, af, bf + 6);                    \
                }                                                               \
            }                                                                   \
        } while (0)

        uint32_t ph[28];

        // prefetch slab p=h0+4 (input row u=h0+3) during kh=0 group
        if (same) pf_issue(ph, x, n, h0 + 3, cib, lane, (h0 + 3) < HW);

        GEMM_BLOCK(0, 0); GEMM_BLOCK(0, 1); GEMM_BLOCK(0, 2);
        __syncthreads();               // slab h0 (slot h0&3) now vacated
        if (same) {
            pf_store(sb + OFF_SLAB + (uint32_t)((h0 + 4) & 3) * SLAB_STRIDE,
                     ph, cib, lane);
            // prefetch slab p=h0+5 (input row u=h0+4) during kh=1 group
            pf_issue(ph, x, n, h0 + 4, cib, lane, (h0 + 4) < HW);
        }

        GEMM_BLOCK(1, 0); GEMM_BLOCK(1, 1); GEMM_BLOCK(1, 2);
        __syncthreads();               // slab h0+1 (slot (h0+1)&3) now vacated
        if (same) {
            pf_store(sb + OFF_SLAB + (uint32_t)((h0 + 5) & 3) * SLAB_STRIDE,
                     ph, cib, lane);
        }

        GEMM_BLOCK(2, 0); GEMM_BLOCK(2, 1); GEMM_BLOCK(2, 2);
        #undef GEMM_BLOCK

        // epilogue: acc*alpha + bias -> out[n][co][h0+r_sel][w]
        // constants reloaded from SMEM here (keeps them out of the main live set)
        {
            const int q2 = (lane & 3) * 2;
            float* orow = out + (size_t)n * NCHW1
                        + (size_t)(h0 + r_sel) * HW + (lane >> 2);
            #pragma unroll
            for (int nn = 0; nn < 4; nn++) {
                #pragma unroll
                for (int b = 0; b < 2; b++) {
                    const int co = nbase + nn * 8 + q2 + b;
                    const float a =
                        *reinterpret_cast<const float*>(smem + OFF_CONST + co * 4);
                    const float bv =
                        *reinterpret_cast<const float*>(smem + OFF_CONST + 256 + co * 4);
                    float* pc = orow + (size_t)co * NHW;
                    #pragma unroll
                    for (int i = 0; i < 7; i++) {
                        #pragma unroll
                        for (int rh = 0; rh < 2; rh++) {
                            pc[mbase + i * 16 + rh * 8] =
                                acc[i * 16 + nn * 4 + rh * 2 + b] * a + bv;
                        }
                    }
                }
            }
        }

        have = same;
    }
}

// ============================================================================
// kernel_launch
// ============================================================================
extern "C" void kernel_launch(void* const* d_in, const int* in_sizes, int n_in,
                              void* d_out, int out_size) {
    const float* x    = (const float*)d_in[0];
    const float* wgt  = (const float*)d_in[1];
    const float* bias = (const float*)d_in[2];
    float* out = (float*)d_out;

    int dev = 0;
    cudaGetDevice(&dev);
    int sms = 0;
    cudaDeviceGetAttribute(&sms, cudaDevAttrMultiProcessorCount, dev);
    if (sms <= 0) sms = 148;

    cudaFuncSetAttribute(ternary_conv_kernel,
                         cudaFuncAttributeMaxDynamicSharedMemorySize, SMEM_BYTES);

    prep_ternarize<<<64, 256>>>(wgt);
    ternary_conv_kernel<<<sms, 256, SMEM_BYTES>>>(x, bias, out);
}